// round 11
// baseline (speedup 1.0000x reference)
#include <cuda_runtime.h>
#include <cstdint>
#include <cstddef>

#define NN 8192
#define KC 16
#define DD 64

// bilinear tensor-core tiling
#define MT 64                      // rows per mtile
#define KT 64                      // j-cols per kchunk
#define NM (NN / MT)               // 128 mtiles
#define NKC (NN / KT)              // 128 kchunks
#define NITEMS (NM * NKC)          // 16384
#define GRID2 592                  // 4 blocks/SM * 148
#define TPB2 128                   // 4 warps

// dynamic smem layout (float offsets), total 12288 floats = 48KB
#define SA_OFF(buf)  ((buf) * 4096)
#define SBH_OFF(buf) (8192 + (buf) * 1024)
#define SBL_OFF(buf) (10240 + (buf) * 1024)
#define SMEM_FLOATS 12288

static __device__ __align__(16) float g_uhiT[KC][NN];   // tf32-hi of pi, [k][j]
static __device__ __align__(16) float g_uloT[KC][NN];   // residual lo, [k][j]
static __device__ __align__(16) float g_v[NN * KC];     // v[i][k]
static __device__ float g_partials[GRID2];

// ------------------------------------------------------------------
// helpers
// ------------------------------------------------------------------
__device__ __forceinline__ void cp16(void* dst_smem, const void* src_gmem) {
    uint32_t d = (uint32_t)__cvta_generic_to_shared(dst_smem);
    asm volatile("cp.async.cg.shared.global [%0], [%1], 16;" :: "r"(d), "l"(src_gmem));
}
__device__ __forceinline__ uint32_t tf32_hi(float x) {
    uint32_t r;
    asm("cvt.rna.tf32.f32 %0, %1;" : "=r"(r) : "f"(x));
    return r;
}
__device__ __forceinline__ void mma_tf32(float* c, const uint32_t* a,
                                         uint32_t b0, uint32_t b1) {
    asm volatile(
        "mma.sync.aligned.m16n8k8.row.col.f32.tf32.tf32.f32 "
        "{%0,%1,%2,%3}, {%4,%5,%6,%7}, {%8,%9}, {%0,%1,%2,%3};"
        : "+f"(c[0]), "+f"(c[1]), "+f"(c[2]), "+f"(c[3])
        : "r"(a[0]), "r"(a[1]), "r"(a[2]), "r"(a[3]), "r"(b0), "r"(b1));
}

// ------------------------------------------------------------------
// Kernel 1: distances -> softmax pi -> write uhiT/uloT (tf32 split) and v
// 128 threads = 16 k-lanes x 8 node-slots, 2 nodes per thread; grid 512
// ------------------------------------------------------------------
__global__ void __launch_bounds__(TPB2)
pi_kernel(const float* __restrict__ emb,    // (3, NN, DD)
          const float* __restrict__ comm,   // (KC, DD)
          const float* __restrict__ alpha_p) {
    __shared__ float4 c4s[DD / 4][KC];      // [q][k]
    const int tid  = threadIdx.x;
    const int k    = tid & 15;
    const int nloc = tid >> 4;              // 0..7
    const int n0   = blockIdx.x * 16 + nloc;
    const int n1   = n0 + 8;

    for (int idx = tid; idx < 256; idx += TPB2) {
        const int kk = idx >> 4;
        const int q  = idx & 15;
        c4s[q][kk] = reinterpret_cast<const float4*>(comm)[kk * 16 + q];
    }
    __syncthreads();

    const float LOR_MIN = (float)(1.0 + 1e-7);
    const float CLIP_LO = (float)(-1.0 + 1e-7);
    const float CLIP_HI = (float)(1.0 - 1e-7);

    const float4* A0 = reinterpret_cast<const float4*>(emb) + (size_t)n0 * 16;
    const float4* B0 = A0 + (size_t)NN * 16;
    const float4* C0 = B0 + (size_t)NN * 16;
    const float4* A1 = reinterpret_cast<const float4*>(emb) + (size_t)n1 * 16;
    const float4* B1 = A1 + (size_t)NN * 16;
    const float4* C1 = B1 + (size_t)NN * 16;

    float dE0 = 0.f, xn0 = 0.f, dL0 = 0.f, dS0 = 0.f;
    float dE1 = 0.f, xn1 = 0.f, dL1 = 0.f, dS1 = 0.f;
    float cn = 0.f;

    #pragma unroll
    for (int q = 0; q < 16; ++q) {
        float4 c = c4s[q][k];
        cn = fmaf(c.x, c.x, cn);
        cn = fmaf(c.y, c.y, cn);
        cn = fmaf(c.z, c.z, cn);
        cn = fmaf(c.w, c.w, cn);

        float4 a = A0[q];
        dE0 = fmaf(a.x, c.x, dE0); dE0 = fmaf(a.y, c.y, dE0);
        dE0 = fmaf(a.z, c.z, dE0); dE0 = fmaf(a.w, c.w, dE0);
        xn0 = fmaf(a.x, a.x, xn0); xn0 = fmaf(a.y, a.y, xn0);
        xn0 = fmaf(a.z, a.z, xn0); xn0 = fmaf(a.w, a.w, xn0);
        float4 b = B0[q];
        dL0 = fmaf(b.x, c.x, dL0); dL0 = fmaf(b.y, c.y, dL0);
        dL0 = fmaf(b.z, c.z, dL0); dL0 = fmaf(b.w, c.w, dL0);
        float4 d = C0[q];
        dS0 = fmaf(d.x, c.x, dS0); dS0 = fmaf(d.y, c.y, dS0);
        dS0 = fmaf(d.z, c.z, dS0); dS0 = fmaf(d.w, c.w, dS0);

        float4 a1 = A1[q];
        dE1 = fmaf(a1.x, c.x, dE1); dE1 = fmaf(a1.y, c.y, dE1);
        dE1 = fmaf(a1.z, c.z, dE1); dE1 = fmaf(a1.w, c.w, dE1);
        xn1 = fmaf(a1.x, a1.x, xn1); xn1 = fmaf(a1.y, a1.y, xn1);
        xn1 = fmaf(a1.z, a1.z, xn1); xn1 = fmaf(a1.w, a1.w, xn1);
        float4 b1 = B1[q];
        dL1 = fmaf(b1.x, c.x, dL1); dL1 = fmaf(b1.y, c.y, dL1);
        dL1 = fmaf(b1.z, c.z, dL1); dL1 = fmaf(b1.w, c.w, dL1);
        float4 d1 = C1[q];
        dS1 = fmaf(d1.x, c.x, dS1); dS1 = fmaf(d1.y, c.y, dS1);
        dS1 = fmaf(d1.z, c.z, dS1); dS1 = fmaf(d1.w, c.w, dS1);
    }

    const float c00 = c4s[0][k].x;

    float d2_0 = fmaxf(xn0 - 2.f * dE0 + cn, 0.f);
    float d2_1 = fmaxf(xn1 - 2.f * dE1 + cn, 0.f);

    float lip0 = dL0 - 2.f * B0[0].x * c00;
    float lip1 = dL1 - 2.f * B1[0].x * c00;
    float dl0 = acoshf(fmaxf(-lip0, LOR_MIN));
    float dl1 = acoshf(fmaxf(-lip1, LOR_MIN));
    d2_0 = fmaf(dl0, dl0, d2_0);
    d2_1 = fmaf(dl1, dl1, d2_1);

    float ds0 = acosf(fminf(fmaxf(dS0, CLIP_LO), CLIP_HI));
    float ds1 = acosf(fminf(fmaxf(dS1, CLIP_LO), CLIP_HI));
    d2_0 = fmaf(ds0, ds0, d2_0);
    d2_1 = fmaf(ds1, ds1, d2_1);

    const float dn0 = sqrtf(d2_0);
    const float dn1 = sqrtf(d2_1);

    float m0 = dn0, m1 = dn1;
    #pragma unroll
    for (int off = 8; off >= 1; off >>= 1) {
        m0 = fmaxf(m0, __shfl_xor_sync(0xffffffffu, m0, off, 16));
        m1 = fmaxf(m1, __shfl_xor_sync(0xffffffffu, m1, off, 16));
    }
    float e0 = expf(dn0 - m0);
    float e1 = expf(dn1 - m1);
    float es0 = e0, es1 = e1;
    #pragma unroll
    for (int off = 8; off >= 1; off >>= 1) {
        es0 += __shfl_xor_sync(0xffffffffu, es0, off, 16);
        es1 += __shfl_xor_sync(0xffffffffu, es1, off, 16);
    }
    const float pi0 = e0 / es0;
    const float pi1 = e1 / es1;

    const float a  = alpha_p[0];
    const float c1 = a * (1.f / ((float)KC * (float)NN));        // alpha/(K*N)
    const float c2 = 1.f / ((float)KC * (float)KC * (float)NN);  // 1/(K*K*N); sum_k pi = 1

    const float h0 = __uint_as_float(tf32_hi(pi0));
    const float h1 = __uint_as_float(tf32_hi(pi1));
    g_uhiT[k][n0] = h0;
    g_uhiT[k][n1] = h1;
    g_uloT[k][n0] = pi0 - h0;
    g_uloT[k][n1] = pi1 - h1;
    g_v[(size_t)n0 * KC + k] = fmaf(c1, pi0, -c2);
    g_v[(size_t)n1 * KC + k] = fmaf(c1, pi1, -c2);
}

// ------------------------------------------------------------------
// Kernel 2: persistent tf32 MMA. item = (mtile, kchunk); 4 warps x 16 rows.
// A (R tile) split hi/lo on the fly; B = uhiT/uloT. C contracted with v
// at mtile boundaries (linearity), scalar per warp.
// ------------------------------------------------------------------
__global__ void __launch_bounds__(TPB2)
bilinear_kernel(const float* __restrict__ R) {
    extern __shared__ __align__(16) float sm[];
    __shared__ float red[4];

    const int tid  = threadIdx.x;
    const int warp = tid >> 5;
    const int lane = tid & 31;
    const int b    = blockIdx.x;
    const int start = (int)(((long long)b * NITEMS) / GRID2);
    const int end   = (int)(((long long)(b + 1) * NITEMS) / GRID2);

    float acc[2][4] = {{0.f, 0.f, 0.f, 0.f}, {0.f, 0.f, 0.f, 0.f}};
    float scalar = 0.f;

    #define ISSUE(it, buf) do {                                               \
        const int m_ = (it) >> 7, kc_ = (it) & 127;                           \
        const float* Rb_ = R + (size_t)m_ * MT * NN + (size_t)kc_ * KT;       \
        _Pragma("unroll")                                                     \
        for (int c = 0; c < 8; ++c) {                                         \
            int cid = c * TPB2 + tid;                                         \
            int i  = cid >> 4, jc = cid & 15;                                 \
            int w_ = i >> 4, ri = i & 15;                                     \
            int s_ = jc >> 1, r_ = (ri >> 3) + ((jc & 1) << 1);               \
            int sidx = ((w_ * 8 + s_) * 4 + r_) * 8 + (ri & 7);               \
            cp16(sm + SA_OFF(buf) + sidx * 4, Rb_ + (size_t)i * NN + jc * 4); \
        }                                                                     \
        _Pragma("unroll")                                                     \
        for (int c = 0; c < 2; ++c) {                                         \
            int cid = c * TPB2 + tid;                                         \
            int n_ = cid >> 4, jc = cid & 15;                                 \
            int s_ = jc >> 1, r_ = jc & 1, nh_ = n_ >> 3;                     \
            int sidx = ((s_ * 2 + nh_) * 2 + r_) * 8 + (n_ & 7);              \
            cp16(sm + SBH_OFF(buf) + sidx * 4,                                \
                 &g_uhiT[n_][kc_ * KT + jc * 4]);                             \
            cp16(sm + SBL_OFF(buf) + sidx * 4,                                \
                 &g_uloT[n_][kc_ * KT + jc * 4]);                             \
        }                                                                     \
        asm volatile("cp.async.commit_group;" ::: "memory");                  \
    } while (0)

    if (start < end) ISSUE(start, 0);

    for (int it = start; it < end; ++it) {
        const int buf = (it - start) & 1;
        const int m = it >> 7;

        asm volatile("cp.async.wait_group 0;" ::: "memory");
        __syncthreads();
        if (it + 1 < end) ISSUE(it + 1, buf ^ 1);

        const float* sA  = sm + SA_OFF(buf) + warp * 1024;
        const float* sBH = sm + SBH_OFF(buf);
        const float* sBL = sm + SBL_OFF(buf);

        #pragma unroll
        for (int s = 0; s < 8; ++s) {
            uint32_t ah[4], al[4];
            #pragma unroll
            for (int r = 0; r < 4; ++r) {
                float av = sA[(s * 4 + r) * 32 + lane];
                uint32_t hi = tf32_hi(av);
                ah[r] = hi;
                al[r] = __float_as_uint(av - __uint_as_float(hi));
            }
            #pragma unroll
            for (int nh = 0; nh < 2; ++nh) {
                uint32_t bh0 = __float_as_uint(sBH[((s * 2 + nh) * 2 + 0) * 32 + lane]);
                uint32_t bh1 = __float_as_uint(sBH[((s * 2 + nh) * 2 + 1) * 32 + lane]);
                uint32_t bl0 = __float_as_uint(sBL[((s * 2 + nh) * 2 + 0) * 32 + lane]);
                uint32_t bl1 = __float_as_uint(sBL[((s * 2 + nh) * 2 + 1) * 32 + lane]);
                mma_tf32(acc[nh], ah, bh0, bh1);
                mma_tf32(acc[nh], al, bh0, bh1);
                mma_tf32(acc[nh], ah, bl0, bl1);
            }
        }

        // contract partial T with v at mtile boundary (linearity)
        if (it + 1 == end || ((it + 1) >> 7) != m) {
            const int row0 = m * MT + warp * 16 + (lane >> 2);
            const int colb = 2 * (lane & 3);
            #pragma unroll
            for (int nh = 0; nh < 2; ++nh) {
                const float* vb = g_v + (size_t)row0 * KC + nh * 8 + colb;
                scalar = fmaf(acc[nh][0], vb[0], scalar);
                scalar = fmaf(acc[nh][1], vb[1], scalar);
                scalar = fmaf(acc[nh][2], vb[8 * KC], scalar);
                scalar = fmaf(acc[nh][3], vb[8 * KC + 1], scalar);
                acc[nh][0] = 0.f; acc[nh][1] = 0.f;
                acc[nh][2] = 0.f; acc[nh][3] = 0.f;
            }
        }
    }
    #undef ISSUE

    // warp reduce (fixed order), then block reduce
    #pragma unroll
    for (int off = 16; off >= 1; off >>= 1)
        scalar += __shfl_down_sync(0xffffffffu, scalar, off);
    if (lane == 0) red[warp] = scalar;
    __syncthreads();
    if (tid == 0)
        g_partials[b] = (red[0] + red[1]) + (red[2] + red[3]);
}

// ------------------------------------------------------------------
// Kernel 3: finalize — sum GRID2 partials, write scalar
// ------------------------------------------------------------------
__global__ void __launch_bounds__(256)
finalize_kernel(float* __restrict__ out) {
    __shared__ float red[256];
    const int tid = threadIdx.x;
    float a = 0.f;
    for (int i = tid; i < GRID2; i += 256) a += g_partials[i];
    red[tid] = a;
    __syncthreads();
    #pragma unroll
    for (int off = 128; off >= 1; off >>= 1) {
        if (tid < off) red[tid] += red[tid + off];
        __syncthreads();
    }
    if (tid == 0) out[0] = red[0];
}

// ------------------------------------------------------------------
extern "C" void kernel_launch(void* const* d_in, const int* in_sizes, int n_in,
                              void* d_out, int out_size) {
    const float* emb   = (const float*)d_in[0];   // (3, 8192, 64)
    const float* comm  = (const float*)d_in[1];   // (16, 64)
    const float* ricci = (const float*)d_in[2];   // (8192, 8192)
    const float* alpha = (const float*)d_in[3];   // scalar
    float* out = (float*)d_out;

    // opt-in for 48KB dynamic smem (+16B static red[]) — proven harness-safe
    // in earlier rounds; without it the launch fails (total > 48KB default).
    cudaFuncSetAttribute(bilinear_kernel,
                         cudaFuncAttributeMaxDynamicSharedMemorySize,
                         SMEM_FLOATS * (int)sizeof(float));

    pi_kernel<<<NN / 16, TPB2>>>(emb, comm, alpha);
    bilinear_kernel<<<GRID2, TPB2, SMEM_FLOATS * sizeof(float)>>>(ricci);
    finalize_kernel<<<1, 256>>>(out);
}

// round 13
// speedup vs baseline: 1.0541x; 1.0541x over previous
#include <cuda_runtime.h>
#include <cstdint>
#include <cstddef>

#define NN 8192
#define KC 16
#define DD 64

#define TSZ 64                       // tile size
#define NTILE (NN / TSZ)             // 128
#define NPAIR (NTILE * (NTILE + 1) / 2)   // 8256
#define GRIDB 444                    // 3 blocks/SM * 148
#define TPB 256
#define TPAD 72                      // t row stride (floats)

static __device__ __align__(16) float g_piT[KC][NN];   // pi transposed: [k][j]
static __device__ float g_partials[GRIDB];

// ------------------------------------------------------------------
// Kernel 1: distances -> softmax pi -> write piT
// 256 threads = 16 k-lanes x 16 node-slots, 2 nodes per thread (ILP)
// ------------------------------------------------------------------
__global__ void __launch_bounds__(256)
pi_kernel(const float* __restrict__ emb,    // (3, NN, DD)
          const float* __restrict__ comm,   // (KC, DD)
          const float* __restrict__ alpha_p) {
    __shared__ float4 c4s[DD / 4][KC];      // [q][k]
    const int tid  = threadIdx.x;
    const int k    = tid & 15;
    const int nloc = tid >> 4;
    const int n0   = blockIdx.x * 32 + nloc;
    const int n1   = n0 + 16;
    (void)alpha_p;

    {
        const int kk = tid >> 4;
        const int q  = tid & 15;
        c4s[q][kk] = reinterpret_cast<const float4*>(comm)[kk * 16 + q];
    }
    __syncthreads();

    const float LOR_MIN = (float)(1.0 + 1e-7);
    const float CLIP_LO = (float)(-1.0 + 1e-7);
    const float CLIP_HI = (float)(1.0 - 1e-7);

    const float4* A0 = reinterpret_cast<const float4*>(emb) + (size_t)n0 * 16;
    const float4* B0 = A0 + (size_t)NN * 16;
    const float4* C0 = B0 + (size_t)NN * 16;
    const float4* A1 = reinterpret_cast<const float4*>(emb) + (size_t)n1 * 16;
    const float4* B1 = A1 + (size_t)NN * 16;
    const float4* C1 = B1 + (size_t)NN * 16;

    float dE0 = 0.f, xn0 = 0.f, dL0 = 0.f, dS0 = 0.f;
    float dE1 = 0.f, xn1 = 0.f, dL1 = 0.f, dS1 = 0.f;
    float cn = 0.f;

    #pragma unroll
    for (int q = 0; q < 16; ++q) {
        float4 c = c4s[q][k];
        cn = fmaf(c.x, c.x, cn); cn = fmaf(c.y, c.y, cn);
        cn = fmaf(c.z, c.z, cn); cn = fmaf(c.w, c.w, cn);

        float4 a = A0[q];
        dE0 = fmaf(a.x, c.x, dE0); dE0 = fmaf(a.y, c.y, dE0);
        dE0 = fmaf(a.z, c.z, dE0); dE0 = fmaf(a.w, c.w, dE0);
        xn0 = fmaf(a.x, a.x, xn0); xn0 = fmaf(a.y, a.y, xn0);
        xn0 = fmaf(a.z, a.z, xn0); xn0 = fmaf(a.w, a.w, xn0);
        float4 b = B0[q];
        dL0 = fmaf(b.x, c.x, dL0); dL0 = fmaf(b.y, c.y, dL0);
        dL0 = fmaf(b.z, c.z, dL0); dL0 = fmaf(b.w, c.w, dL0);
        float4 d = C0[q];
        dS0 = fmaf(d.x, c.x, dS0); dS0 = fmaf(d.y, c.y, dS0);
        dS0 = fmaf(d.z, c.z, dS0); dS0 = fmaf(d.w, c.w, dS0);

        float4 a1 = A1[q];
        dE1 = fmaf(a1.x, c.x, dE1); dE1 = fmaf(a1.y, c.y, dE1);
        dE1 = fmaf(a1.z, c.z, dE1); dE1 = fmaf(a1.w, c.w, dE1);
        xn1 = fmaf(a1.x, a1.x, xn1); xn1 = fmaf(a1.y, a1.y, xn1);
        xn1 = fmaf(a1.z, a1.z, xn1); xn1 = fmaf(a1.w, a1.w, xn1);
        float4 b1 = B1[q];
        dL1 = fmaf(b1.x, c.x, dL1); dL1 = fmaf(b1.y, c.y, dL1);
        dL1 = fmaf(b1.z, c.z, dL1); dL1 = fmaf(b1.w, c.w, dL1);
        float4 d1 = C1[q];
        dS1 = fmaf(d1.x, c.x, dS1); dS1 = fmaf(d1.y, c.y, dS1);
        dS1 = fmaf(d1.z, c.z, dS1); dS1 = fmaf(d1.w, c.w, dS1);
    }

    const float c00 = c4s[0][k].x;

    float d2_0 = fmaxf(xn0 - 2.f * dE0 + cn, 0.f);
    float d2_1 = fmaxf(xn1 - 2.f * dE1 + cn, 0.f);

    float lip0 = dL0 - 2.f * B0[0].x * c00;
    float lip1 = dL1 - 2.f * B1[0].x * c00;
    float dl0 = acoshf(fmaxf(-lip0, LOR_MIN));
    float dl1 = acoshf(fmaxf(-lip1, LOR_MIN));
    d2_0 = fmaf(dl0, dl0, d2_0);
    d2_1 = fmaf(dl1, dl1, d2_1);

    float ds0 = acosf(fminf(fmaxf(dS0, CLIP_LO), CLIP_HI));
    float ds1 = acosf(fminf(fmaxf(dS1, CLIP_LO), CLIP_HI));
    d2_0 = fmaf(ds0, ds0, d2_0);
    d2_1 = fmaf(ds1, ds1, d2_1);

    const float dn0 = sqrtf(d2_0);
    const float dn1 = sqrtf(d2_1);

    float m0 = dn0, m1 = dn1;
    #pragma unroll
    for (int off = 8; off >= 1; off >>= 1) {
        m0 = fmaxf(m0, __shfl_xor_sync(0xffffffffu, m0, off, 16));
        m1 = fmaxf(m1, __shfl_xor_sync(0xffffffffu, m1, off, 16));
    }
    float e0 = expf(dn0 - m0);
    float e1 = expf(dn1 - m1);
    float es0 = e0, es1 = e1;
    #pragma unroll
    for (int off = 8; off >= 1; off >>= 1) {
        es0 += __shfl_xor_sync(0xffffffffu, es0, off, 16);
        es1 += __shfl_xor_sync(0xffffffffu, es1, off, 16);
    }
    g_piT[k][n0] = e0 / es0;
    g_piT[k][n1] = e1 / es1;
}

// ------------------------------------------------------------------
// Kernel 2: symmetric tile-pair bilinear.
//   t_ij = c1*(pi_i . pi_j) - c2  (symmetric; sum_k pi = 1)
//   total = sum_ij r_ij t_ij
// item = tile pair (TI <= TJ); phase1 builds t & tT in smem;
// phase2 streams R[TI,TJ] (+ R[TJ,TI] off-diag), 1 FMA per element.
// ------------------------------------------------------------------
__global__ void __launch_bounds__(TPB, 3)
bilinear_kernel(const float* __restrict__ R,
                const float* __restrict__ alpha_p) {
    __shared__ __align__(16) float st [TSZ][TPAD];   // 18KB
    __shared__ __align__(16) float stT[TSZ][TPAD];   // 18KB
    __shared__ __align__(16) float spiI[KC][TSZ];    // 4KB [k][i]
    __shared__ __align__(16) float spiJ[KC][TSZ];    // 4KB [k][j]
    __shared__ float red[TPB];

    const int tid = threadIdx.x;
    const int b   = blockIdx.x;

    const float c1 = alpha_p[0] * (1.f / ((float)KC * (float)NN));
    const float c2 = 1.f / ((float)KC * (float)KC * (float)NN);

    const int start = (int)(((long long)b * NPAIR) / GRIDB);
    const int end   = (int)(((long long)(b + 1) * NPAIR) / GRIDB);

    // decode first (ti, tj): base(r) = r*NTILE - r*(r-1)/2
    int ti = 0;
    while ((ti + 1) * NTILE - ((ti + 1) * ti) / 2 <= start) ++ti;
    int tj = ti + (start - (ti * NTILE - (ti * (ti - 1)) / 2));

    // phase-1 mapping
    const int a1i = tid >> 4;          // i-quad 0..15
    const int b1j = tid & 15;          // j-quad 0..15
    // phase-2 mapping
    const int i2 = tid >> 2;           // row 0..63
    const int q2 = tid & 3;            // 16-col chunk 0..3

    const float4* piT4 = reinterpret_cast<const float4*>(&g_piT[0][0]);

    float total = 0.f;

    for (int item = start; item < end; ++item) {
        // ---- stage pi tiles (also acts as barrier before t overwrite) ----
        {
            const int k = tid >> 4;    // 0..15
            const int c = tid & 15;    // f4 index 0..15
            *reinterpret_cast<float4*>(&spiI[k][c * 4]) =
                piT4[(size_t)k * (NN / 4) + ti * (TSZ / 4) + c];
            *reinterpret_cast<float4*>(&spiJ[k][c * 4]) =
                piT4[(size_t)k * (NN / 4) + tj * (TSZ / 4) + c];
        }
        __syncthreads();

        // ---- phase 1: t tile (4x4 register block per thread) ----
        float4 acc0 = make_float4(0.f, 0.f, 0.f, 0.f);
        float4 acc1 = make_float4(0.f, 0.f, 0.f, 0.f);
        float4 acc2 = make_float4(0.f, 0.f, 0.f, 0.f);
        float4 acc3 = make_float4(0.f, 0.f, 0.f, 0.f);
        #pragma unroll
        for (int k = 0; k < KC; ++k) {
            float4 vi = *reinterpret_cast<const float4*>(&spiI[k][a1i * 4]);
            float4 vj = *reinterpret_cast<const float4*>(&spiJ[k][b1j * 4]);
            acc0.x = fmaf(vi.x, vj.x, acc0.x); acc0.y = fmaf(vi.x, vj.y, acc0.y);
            acc0.z = fmaf(vi.x, vj.z, acc0.z); acc0.w = fmaf(vi.x, vj.w, acc0.w);
            acc1.x = fmaf(vi.y, vj.x, acc1.x); acc1.y = fmaf(vi.y, vj.y, acc1.y);
            acc1.z = fmaf(vi.y, vj.z, acc1.z); acc1.w = fmaf(vi.y, vj.w, acc1.w);
            acc2.x = fmaf(vi.z, vj.x, acc2.x); acc2.y = fmaf(vi.z, vj.y, acc2.y);
            acc2.z = fmaf(vi.z, vj.z, acc2.z); acc2.w = fmaf(vi.z, vj.w, acc2.w);
            acc3.x = fmaf(vi.w, vj.x, acc3.x); acc3.y = fmaf(vi.w, vj.y, acc3.y);
            acc3.z = fmaf(vi.w, vj.z, acc3.z); acc3.w = fmaf(vi.w, vj.w, acc3.w);
        }
        // affine transform: t = c1*P - c2
        acc0.x = fmaf(c1, acc0.x, -c2); acc0.y = fmaf(c1, acc0.y, -c2);
        acc0.z = fmaf(c1, acc0.z, -c2); acc0.w = fmaf(c1, acc0.w, -c2);
        acc1.x = fmaf(c1, acc1.x, -c2); acc1.y = fmaf(c1, acc1.y, -c2);
        acc1.z = fmaf(c1, acc1.z, -c2); acc1.w = fmaf(c1, acc1.w, -c2);
        acc2.x = fmaf(c1, acc2.x, -c2); acc2.y = fmaf(c1, acc2.y, -c2);
        acc2.z = fmaf(c1, acc2.z, -c2); acc2.w = fmaf(c1, acc2.w, -c2);
        acc3.x = fmaf(c1, acc3.x, -c2); acc3.y = fmaf(c1, acc3.y, -c2);
        acc3.z = fmaf(c1, acc3.z, -c2); acc3.w = fmaf(c1, acc3.w, -c2);

        // store t rows and tT rows
        *reinterpret_cast<float4*>(&st[a1i * 4 + 0][b1j * 4]) = acc0;
        *reinterpret_cast<float4*>(&st[a1i * 4 + 1][b1j * 4]) = acc1;
        *reinterpret_cast<float4*>(&st[a1i * 4 + 2][b1j * 4]) = acc2;
        *reinterpret_cast<float4*>(&st[a1i * 4 + 3][b1j * 4]) = acc3;
        *reinterpret_cast<float4*>(&stT[b1j * 4 + 0][a1i * 4]) =
            make_float4(acc0.x, acc1.x, acc2.x, acc3.x);
        *reinterpret_cast<float4*>(&stT[b1j * 4 + 1][a1i * 4]) =
            make_float4(acc0.y, acc1.y, acc2.y, acc3.y);
        *reinterpret_cast<float4*>(&stT[b1j * 4 + 2][a1i * 4]) =
            make_float4(acc0.z, acc1.z, acc2.z, acc3.z);
        *reinterpret_cast<float4*>(&stT[b1j * 4 + 3][a1i * 4]) =
            make_float4(acc0.w, acc1.w, acc2.w, acc3.w);
        __syncthreads();

        // ---- phase 2: contract with R tiles ----
        {
            const float* Ap = R + (size_t)(ti * TSZ + i2) * NN + tj * TSZ + q2 * 16;
            float4 x0 = *reinterpret_cast<const float4*>(Ap + 0);
            float4 x1 = *reinterpret_cast<const float4*>(Ap + 4);
            float4 x2 = *reinterpret_cast<const float4*>(Ap + 8);
            float4 x3 = *reinterpret_cast<const float4*>(Ap + 12);
            float4 t0 = *reinterpret_cast<const float4*>(&st[i2][q2 * 16 + 0]);
            float4 t1 = *reinterpret_cast<const float4*>(&st[i2][q2 * 16 + 4]);
            float4 t2 = *reinterpret_cast<const float4*>(&st[i2][q2 * 16 + 8]);
            float4 t3 = *reinterpret_cast<const float4*>(&st[i2][q2 * 16 + 12]);
            total = fmaf(x0.x, t0.x, total); total = fmaf(x0.y, t0.y, total);
            total = fmaf(x0.z, t0.z, total); total = fmaf(x0.w, t0.w, total);
            total = fmaf(x1.x, t1.x, total); total = fmaf(x1.y, t1.y, total);
            total = fmaf(x1.z, t1.z, total); total = fmaf(x1.w, t1.w, total);
            total = fmaf(x2.x, t2.x, total); total = fmaf(x2.y, t2.y, total);
            total = fmaf(x2.z, t2.z, total); total = fmaf(x2.w, t2.w, total);
            total = fmaf(x3.x, t3.x, total); total = fmaf(x3.y, t3.y, total);
            total = fmaf(x3.z, t3.z, total); total = fmaf(x3.w, t3.w, total);
        }
        if (ti != tj) {
            const float* Bp = R + (size_t)(tj * TSZ + i2) * NN + ti * TSZ + q2 * 16;
            float4 x0 = *reinterpret_cast<const float4*>(Bp + 0);
            float4 x1 = *reinterpret_cast<const float4*>(Bp + 4);
            float4 x2 = *reinterpret_cast<const float4*>(Bp + 8);
            float4 x3 = *reinterpret_cast<const float4*>(Bp + 12);
            float4 t0 = *reinterpret_cast<const float4*>(&stT[i2][q2 * 16 + 0]);
            float4 t1 = *reinterpret_cast<const float4*>(&stT[i2][q2 * 16 + 4]);
            float4 t2 = *reinterpret_cast<const float4*>(&stT[i2][q2 * 16 + 8]);
            float4 t3 = *reinterpret_cast<const float4*>(&stT[i2][q2 * 16 + 12]);
            total = fmaf(x0.x, t0.x, total); total = fmaf(x0.y, t0.y, total);
            total = fmaf(x0.z, t0.z, total); total = fmaf(x0.w, t0.w, total);
            total = fmaf(x1.x, t1.x, total); total = fmaf(x1.y, t1.y, total);
            total = fmaf(x1.z, t1.z, total); total = fmaf(x1.w, t1.w, total);
            total = fmaf(x2.x, t2.x, total); total = fmaf(x2.y, t2.y, total);
            total = fmaf(x2.z, t2.z, total); total = fmaf(x2.w, t2.w, total);
            total = fmaf(x3.x, t3.x, total); total = fmaf(x3.y, t3.y, total);
            total = fmaf(x3.z, t3.z, total); total = fmaf(x3.w, t3.w, total);
        }

        // advance pair
        if (++tj == NTILE) { ++ti; tj = ti; }
    }

    // block reduction (fixed tree -> deterministic)
    red[tid] = total;
    __syncthreads();
    #pragma unroll
    for (int off = TPB / 2; off >= 1; off >>= 1) {
        if (tid < off) red[tid] += red[tid + off];
        __syncthreads();
    }
    if (tid == 0) g_partials[b] = red[0];
}

// ------------------------------------------------------------------
// Kernel 3: finalize — sum GRIDB partials, write scalar
// ------------------------------------------------------------------
__global__ void __launch_bounds__(256)
finalize_kernel(float* __restrict__ out) {
    __shared__ float red[256];
    const int tid = threadIdx.x;
    float a = 0.f;
    for (int i = tid; i < GRIDB; i += 256) a += g_partials[i];
    red[tid] = a;
    __syncthreads();
    #pragma unroll
    for (int off = 128; off >= 1; off >>= 1) {
        if (tid < off) red[tid] += red[tid + off];
        __syncthreads();
    }
    if (tid == 0) out[0] = red[0];
}

// ------------------------------------------------------------------
extern "C" void kernel_launch(void* const* d_in, const int* in_sizes, int n_in,
                              void* d_out, int out_size) {
    const float* emb   = (const float*)d_in[0];   // (3, 8192, 64)
    const float* comm  = (const float*)d_in[1];   // (16, 64)
    const float* ricci = (const float*)d_in[2];   // (8192, 8192)
    const float* alpha = (const float*)d_in[3];   // scalar
    float* out = (float*)d_out;

    pi_kernel<<<NN / 32, 256>>>(emb, comm, alpha);
    bilinear_kernel<<<GRIDB, TPB>>>(ricci, alpha);
    finalize_kernel<<<1, 256>>>(out);
}

// round 14
// speedup vs baseline: 1.5117x; 1.4341x over previous
#include <cuda_runtime.h>
#include <cuda_bf16.h>
#include <cstdint>
#include <cstddef>

#define NN 8192
#define KC 16
#define DD 64

#define MT 128                       // rows per item
#define KT 64                        // j-cols per item
#define NM (NN / MT)                 // 64
#define NJC (NN / KT)                // 128
#define NITEMS (NM * NJC)            // 8192
#define GRIDB 296                    // 2 blocks/SM * 148
#define TPB 256

// U (pi) in bf16 mma-B fragment layout: per (ks, ns, lane) one uint2 {b0,b1}
// ushort index = ((ks*2+ns)*32 + lane)*4 + reg*2 + half
static __device__ __align__(16) unsigned short g_Bhi[(NN / 16) * 2 * 32 * 4];
static __device__ __align__(16) unsigned short g_Blo[(NN / 16) * 2 * 32 * 4];
static __device__ __align__(16) float g_v[NN * KC];    // v[i][k]
static __device__ float g_partials[GRIDB];

// ------------------------------------------------------------------
// helpers
// ------------------------------------------------------------------
__device__ __forceinline__ uint32_t bf2(float lo, float hi) {
    uint32_t r;
    asm("cvt.rn.bf16x2.f32 %0, %1, %2;" : "=r"(r) : "f"(hi), "f"(lo));
    return r;   // low 16 bits = lo, high = hi
}
__device__ __forceinline__ uint32_t bf2lo(float x0, float x1, uint32_t h) {
    float h0 = __uint_as_float(h << 16);
    float h1 = __uint_as_float(h & 0xffff0000u);
    return bf2(x0 - h0, x1 - h1);
}
__device__ __forceinline__ void mma_bf16(float* c, const uint4 a,
                                         uint32_t b0, uint32_t b1) {
    asm volatile(
        "mma.sync.aligned.m16n8k16.row.col.f32.bf16.bf16.f32 "
        "{%0,%1,%2,%3}, {%4,%5,%6,%7}, {%8,%9}, {%0,%1,%2,%3};"
        : "+f"(c[0]), "+f"(c[1]), "+f"(c[2]), "+f"(c[3])
        : "r"(a.x), "r"(a.y), "r"(a.z), "r"(a.w), "r"(b0), "r"(b1));
}
__device__ __forceinline__ void cp16(void* dst_smem, const void* src_gmem) {
    uint32_t d = (uint32_t)__cvta_generic_to_shared(dst_smem);
    asm volatile("cp.async.cg.shared.global [%0], [%1], 16;"
                 :: "r"(d), "l"(src_gmem));
}

// ------------------------------------------------------------------
// Kernel 1: distances -> softmax pi -> U bf16 hi/lo frag layout + v
// 256 threads = 16 k-lanes x 16 node-slots, 2 nodes per thread
// ------------------------------------------------------------------
__global__ void __launch_bounds__(256)
pi_kernel(const float* __restrict__ emb,    // (3, NN, DD)
          const float* __restrict__ comm,   // (KC, DD)
          const float* __restrict__ alpha_p) {
    __shared__ float4 c4s[DD / 4][KC];
    const int tid  = threadIdx.x;
    const int k    = tid & 15;
    const int nloc = tid >> 4;
    const int n0   = blockIdx.x * 32 + nloc;
    const int n1   = n0 + 16;

    {
        const int kk = tid >> 4;
        const int q  = tid & 15;
        c4s[q][kk] = reinterpret_cast<const float4*>(comm)[kk * 16 + q];
    }
    __syncthreads();

    const float LOR_MIN = (float)(1.0 + 1e-7);
    const float CLIP_LO = (float)(-1.0 + 1e-7);
    const float CLIP_HI = (float)(1.0 - 1e-7);

    const float4* A0 = reinterpret_cast<const float4*>(emb) + (size_t)n0 * 16;
    const float4* B0 = A0 + (size_t)NN * 16;
    const float4* C0 = B0 + (size_t)NN * 16;
    const float4* A1 = reinterpret_cast<const float4*>(emb) + (size_t)n1 * 16;
    const float4* B1 = A1 + (size_t)NN * 16;
    const float4* C1 = B1 + (size_t)NN * 16;

    float dE0 = 0.f, xn0 = 0.f, dL0 = 0.f, dS0 = 0.f;
    float dE1 = 0.f, xn1 = 0.f, dL1 = 0.f, dS1 = 0.f;
    float cn = 0.f;

    #pragma unroll
    for (int q = 0; q < 16; ++q) {
        float4 c = c4s[q][k];
        cn = fmaf(c.x, c.x, cn); cn = fmaf(c.y, c.y, cn);
        cn = fmaf(c.z, c.z, cn); cn = fmaf(c.w, c.w, cn);

        float4 a = A0[q];
        dE0 = fmaf(a.x, c.x, dE0); dE0 = fmaf(a.y, c.y, dE0);
        dE0 = fmaf(a.z, c.z, dE0); dE0 = fmaf(a.w, c.w, dE0);
        xn0 = fmaf(a.x, a.x, xn0); xn0 = fmaf(a.y, a.y, xn0);
        xn0 = fmaf(a.z, a.z, xn0); xn0 = fmaf(a.w, a.w, xn0);
        float4 b = B0[q];
        dL0 = fmaf(b.x, c.x, dL0); dL0 = fmaf(b.y, c.y, dL0);
        dL0 = fmaf(b.z, c.z, dL0); dL0 = fmaf(b.w, c.w, dL0);
        float4 d = C0[q];
        dS0 = fmaf(d.x, c.x, dS0); dS0 = fmaf(d.y, c.y, dS0);
        dS0 = fmaf(d.z, c.z, dS0); dS0 = fmaf(d.w, c.w, dS0);

        float4 a1 = A1[q];
        dE1 = fmaf(a1.x, c.x, dE1); dE1 = fmaf(a1.y, c.y, dE1);
        dE1 = fmaf(a1.z, c.z, dE1); dE1 = fmaf(a1.w, c.w, dE1);
        xn1 = fmaf(a1.x, a1.x, xn1); xn1 = fmaf(a1.y, a1.y, xn1);
        xn1 = fmaf(a1.z, a1.z, xn1); xn1 = fmaf(a1.w, a1.w, xn1);
        float4 b1 = B1[q];
        dL1 = fmaf(b1.x, c.x, dL1); dL1 = fmaf(b1.y, c.y, dL1);
        dL1 = fmaf(b1.z, c.z, dL1); dL1 = fmaf(b1.w, c.w, dL1);
        float4 d1 = C1[q];
        dS1 = fmaf(d1.x, c.x, dS1); dS1 = fmaf(d1.y, c.y, dS1);
        dS1 = fmaf(d1.z, c.z, dS1); dS1 = fmaf(d1.w, c.w, dS1);
    }

    const float c00 = c4s[0][k].x;

    float d2_0 = fmaxf(xn0 - 2.f * dE0 + cn, 0.f);
    float d2_1 = fmaxf(xn1 - 2.f * dE1 + cn, 0.f);

    float lip0 = dL0 - 2.f * B0[0].x * c00;
    float lip1 = dL1 - 2.f * B1[0].x * c00;
    float dl0 = acoshf(fmaxf(-lip0, LOR_MIN));
    float dl1 = acoshf(fmaxf(-lip1, LOR_MIN));
    d2_0 = fmaf(dl0, dl0, d2_0);
    d2_1 = fmaf(dl1, dl1, d2_1);

    float ds0 = acosf(fminf(fmaxf(dS0, CLIP_LO), CLIP_HI));
    float ds1 = acosf(fminf(fmaxf(dS1, CLIP_LO), CLIP_HI));
    d2_0 = fmaf(ds0, ds0, d2_0);
    d2_1 = fmaf(ds1, ds1, d2_1);

    const float dn0 = sqrtf(d2_0);
    const float dn1 = sqrtf(d2_1);

    float m0 = dn0, m1 = dn1;
    #pragma unroll
    for (int off = 8; off >= 1; off >>= 1) {
        m0 = fmaxf(m0, __shfl_xor_sync(0xffffffffu, m0, off, 16));
        m1 = fmaxf(m1, __shfl_xor_sync(0xffffffffu, m1, off, 16));
    }
    float e0 = expf(dn0 - m0);
    float e1 = expf(dn1 - m1);
    float es0 = e0, es1 = e1;
    #pragma unroll
    for (int off = 8; off >= 1; off >>= 1) {
        es0 += __shfl_xor_sync(0xffffffffu, es0, off, 16);
        es1 += __shfl_xor_sync(0xffffffffu, es1, off, 16);
    }
    const float pi0 = e0 / es0;
    const float pi1 = e1 / es1;

    const float a  = alpha_p[0];
    const float c1 = a * (1.f / ((float)KC * (float)NN));
    const float c2 = 1.f / ((float)KC * (float)KC * (float)NN);  // sum_k pi == 1

    const int ns = k >> 3;
    const int g  = k & 7;

    // node n0
    {
        __nv_bfloat16 h = __float2bfloat16(pi0);
        __nv_bfloat16 l = __float2bfloat16(pi0 - __bfloat162float(h));
        int jm = n0 & 15, ksg = n0 >> 4;
        int rg = jm >> 3, t = (jm & 7) >> 1, hf = jm & 1;
        size_t u = ((size_t)(ksg * 2 + ns) * 32 + (g * 4 + t)) * 4 + rg * 2 + hf;
        g_Bhi[u] = __bfloat16_as_ushort(h);
        g_Blo[u] = __bfloat16_as_ushort(l);
        g_v[(size_t)n0 * KC + k] = fmaf(c1, pi0, -c2);
    }
    // node n1
    {
        __nv_bfloat16 h = __float2bfloat16(pi1);
        __nv_bfloat16 l = __float2bfloat16(pi1 - __bfloat162float(h));
        int jm = n1 & 15, ksg = n1 >> 4;
        int rg = jm >> 3, t = (jm & 7) >> 1, hf = jm & 1;
        size_t u = ((size_t)(ksg * 2 + ns) * 32 + (g * 4 + t)) * 4 + rg * 2 + hf;
        g_Bhi[u] = __bfloat16_as_ushort(h);
        g_Blo[u] = __bfloat16_as_ushort(l);
        g_v[(size_t)n1 * KC + k] = fmaf(c1, pi1, -c2);
    }
}

// ------------------------------------------------------------------
// Kernel 2: bf16 mma.sync, 3-term split. item = (m, jc) of R (128x64).
// A split hi/lo on the fly into frag-linear smem; B cp.async'd (frag
// layout precomputed). Acc held in regs across items of same m; epilogue
// contracts with v.
// ------------------------------------------------------------------
__global__ void __launch_bounds__(TPB, 2)
bilinear_kernel(const float* __restrict__ R) {
    __shared__ __align__(16) uint4 sAhi[32][32];   // 16KB: [subtile][lane]
    __shared__ __align__(16) uint4 sAlo[32][32];   // 16KB
    __shared__ __align__(16) uint2 sBhi[8][32];    // 2KB: [ki*2+ns][lane]
    __shared__ __align__(16) uint2 sBlo[8][32];    // 2KB
    __shared__ float red[TPB];

    const int tid  = threadIdx.x;
    const int warp = tid >> 5;
    const int lane = tid & 31;
    const int g    = lane >> 2;
    const int t    = lane & 3;
    const int b    = blockIdx.x;

    const int start = (int)(((long long)b * NITEMS) / GRIDB);
    const int end   = (int)(((long long)(b + 1) * NITEMS) / GRIDB);

    float acc0[4] = {0.f, 0.f, 0.f, 0.f};   // ns=0
    float acc1[4] = {0.f, 0.f, 0.f, 0.f};   // ns=1
    float scalar = 0.f;

    for (int item = start; item < end; ++item) {
        const int m  = item >> 7;       // 0..63
        const int jc = item & 127;      // 0..127
        const int jcb = jc * KT;

        __syncthreads();   // previous mma phase done before smem overwrite

        // ---- B: cp.async 4KB (frag layout in gmem) ----
        if (tid < 128) {
            const int klns = tid >> 4;          // 0..7
            const int pr   = tid & 15;          // uint2 pair
            const int ksg  = jc * 4 + (klns >> 1);
            const int ns   = klns & 1;
            const unsigned short* src =
                g_Bhi + ((size_t)(ksg * 2 + ns) * 32 + pr * 2) * 4;
            cp16(&sBhi[klns][pr * 2], src);
        } else {
            const int tt   = tid - 128;
            const int klns = tt >> 4;
            const int pr   = tt & 15;
            const int ksg  = jc * 4 + (klns >> 1);
            const int ns   = klns & 1;
            const unsigned short* src =
                g_Blo + ((size_t)(ksg * 2 + ns) * 32 + pr * 2) * 4;
            cp16(&sBlo[klns][pr * 2], src);
        }
        asm volatile("cp.async.commit_group;" ::: "memory");

        // ---- A: load fp32 R, split bf16 hi/lo, store frag-linear ----
        #pragma unroll
        for (int s = 0; s < 4; ++s) {
            const int sub = s * 8 + warp;       // this warp's subtile
            const int mi = sub >> 2, ki = sub & 3;
            const float* base = R + (size_t)(m * MT + mi * 16 + g) * NN
                                  + jcb + ki * 16 + 2 * t;
            float2 x0 = *reinterpret_cast<const float2*>(base);
            float2 x1 = *reinterpret_cast<const float2*>(base + 8 * NN);
            float2 x2 = *reinterpret_cast<const float2*>(base + 8);
            float2 x3 = *reinterpret_cast<const float2*>(base + 8 * NN + 8);
            uint32_t h0 = bf2(x0.x, x0.y);
            uint32_t h1 = bf2(x1.x, x1.y);
            uint32_t h2 = bf2(x2.x, x2.y);
            uint32_t h3 = bf2(x3.x, x3.y);
            sAhi[sub][lane] = make_uint4(h0, h1, h2, h3);
            sAlo[sub][lane] = make_uint4(bf2lo(x0.x, x0.y, h0),
                                         bf2lo(x1.x, x1.y, h1),
                                         bf2lo(x2.x, x2.y, h2),
                                         bf2lo(x3.x, x3.y, h3));
        }

        asm volatile("cp.async.wait_group 0;" ::: "memory");
        __syncthreads();

        // ---- mma phase: warp w owns m-subtile w, all 4 ki, both ns ----
        #pragma unroll
        for (int ki = 0; ki < 4; ++ki) {
            uint4 ah = sAhi[warp * 4 + ki][lane];
            uint4 al = sAlo[warp * 4 + ki][lane];
            uint2 bh0 = sBhi[ki * 2 + 0][lane];
            uint2 bl0 = sBlo[ki * 2 + 0][lane];
            uint2 bh1 = sBhi[ki * 2 + 1][lane];
            uint2 bl1 = sBlo[ki * 2 + 1][lane];
            mma_bf16(acc0, ah, bh0.x, bh0.y);
            mma_bf16(acc0, al, bh0.x, bh0.y);
            mma_bf16(acc0, ah, bl0.x, bl0.y);
            mma_bf16(acc1, ah, bh1.x, bh1.y);
            mma_bf16(acc1, al, bh1.x, bh1.y);
            mma_bf16(acc1, ah, bl1.x, bl1.y);
        }

        // ---- epilogue at m-range end: contract T with v ----
        if (item + 1 == end || ((item + 1) >> 7) != m) {
            const int row = m * MT + warp * 16 + g;
            const float2* v0 = reinterpret_cast<const float2*>(g_v + (size_t)row * KC);
            const float2* v8 = reinterpret_cast<const float2*>(g_v + (size_t)(row + 8) * KC);
            float2 va = v0[t], vb = v8[t];            // ns0 cols 2t,2t+1
            float2 vc = v0[4 + t], vd = v8[4 + t];    // ns1 cols 8+2t
            scalar = fmaf(acc0[0], va.x, scalar);
            scalar = fmaf(acc0[1], va.y, scalar);
            scalar = fmaf(acc0[2], vb.x, scalar);
            scalar = fmaf(acc0[3], vb.y, scalar);
            scalar = fmaf(acc1[0], vc.x, scalar);
            scalar = fmaf(acc1[1], vc.y, scalar);
            scalar = fmaf(acc1[2], vd.x, scalar);
            scalar = fmaf(acc1[3], vd.y, scalar);
            acc0[0] = acc0[1] = acc0[2] = acc0[3] = 0.f;
            acc1[0] = acc1[1] = acc1[2] = acc1[3] = 0.f;
        }
    }

    // block reduction (fixed tree -> deterministic)
    red[tid] = scalar;
    __syncthreads();
    #pragma unroll
    for (int off = TPB / 2; off >= 1; off >>= 1) {
        if (tid < off) red[tid] += red[tid + off];
        __syncthreads();
    }
    if (tid == 0) g_partials[b] = red[0];
}

// ------------------------------------------------------------------
// Kernel 3: finalize
// ------------------------------------------------------------------
__global__ void __launch_bounds__(256)
finalize_kernel(float* __restrict__ out) {
    __shared__ float red[256];
    const int tid = threadIdx.x;
    float a = 0.f;
    for (int i = tid; i < GRIDB; i += 256) a += g_partials[i];
    red[tid] = a;
    __syncthreads();
    #pragma unroll
    for (int off = 128; off >= 1; off >>= 1) {
        if (tid < off) red[tid] += red[tid + off];
        __syncthreads();
    }
    if (tid == 0) out[0] = red[0];
}

// ------------------------------------------------------------------
extern "C" void kernel_launch(void* const* d_in, const int* in_sizes, int n_in,
                              void* d_out, int out_size) {
    const float* emb   = (const float*)d_in[0];   // (3, 8192, 64)
    const float* comm  = (const float*)d_in[1];   // (16, 64)
    const float* ricci = (const float*)d_in[2];   // (8192, 8192)
    const float* alpha = (const float*)d_in[3];   // scalar
    float* out = (float*)d_out;

    pi_kernel<<<NN / 32, 256>>>(emb, comm, alpha);
    bilinear_kernel<<<GRIDB, TPB>>>(ricci);
    finalize_kernel<<<1, 256>>>(out);
}

// round 16
// speedup vs baseline: 2.0754x; 1.3729x over previous
#include <cuda_runtime.h>
#include <cuda_bf16.h>
#include <cstdint>
#include <cstddef>

#define NN 8192
#define KC 16
#define DD 64

#define MT 128                       // rows per item (8 warps x 16)
#define KT 64                        // j-cols per item (4 ki subtiles)
#define NM (NN / MT)                 // 64
#define NJC (NN / KT)                // 128
#define NITEMS (NM * NJC)            // 8192 (item = m*128 + jc; jc inner)
#define GRIDB 296                    // 2 blocks/SM * 148
#define TPB 256

// U (pi) in bf16 mma-B fragment layout: per (ksg, ns, lane) one uint2 {b0,b1}
// ushort index = ((ksg*2+ns)*32 + lane)*4 + reg*2 + half   (ksg = j/16)
static __device__ __align__(16) unsigned short g_Bhi[(NN / 16) * 2 * 32 * 4];
static __device__ __align__(16) unsigned short g_Blo[(NN / 16) * 2 * 32 * 4];
static __device__ __align__(16) float g_v[NN * KC];    // v[i][k]
static __device__ float g_partials[GRIDB];

// ------------------------------------------------------------------
// helpers
// ------------------------------------------------------------------
__device__ __forceinline__ uint32_t bf2(float lo, float hi) {
    uint32_t r;
    asm("cvt.rn.bf16x2.f32 %0, %1, %2;" : "=r"(r) : "f"(hi), "f"(lo));
    return r;   // low 16 bits = lo, high = hi
}
__device__ __forceinline__ uint32_t bf2lo(float x0, float x1, uint32_t h) {
    float h0 = __uint_as_float(h << 16);
    float h1 = __uint_as_float(h & 0xffff0000u);
    return bf2(x0 - h0, x1 - h1);
}
__device__ __forceinline__ void mma_bf16(float* c, uint32_t a0, uint32_t a1,
                                         uint32_t a2, uint32_t a3,
                                         uint32_t b0, uint32_t b1) {
    asm volatile(
        "mma.sync.aligned.m16n8k16.row.col.f32.bf16.bf16.f32 "
        "{%0,%1,%2,%3}, {%4,%5,%6,%7}, {%8,%9}, {%0,%1,%2,%3};"
        : "+f"(c[0]), "+f"(c[1]), "+f"(c[2]), "+f"(c[3])
        : "r"(a0), "r"(a1), "r"(a2), "r"(a3), "r"(b0), "r"(b1));
}

// ------------------------------------------------------------------
// Kernel 1: distances -> softmax pi -> U bf16 hi/lo frag layout + v
// (identical to the R14 version that passed)
// ------------------------------------------------------------------
__global__ void __launch_bounds__(256)
pi_kernel(const float* __restrict__ emb,    // (3, NN, DD)
          const float* __restrict__ comm,   // (KC, DD)
          const float* __restrict__ alpha_p) {
    __shared__ float4 c4s[DD / 4][KC];
    const int tid  = threadIdx.x;
    const int k    = tid & 15;
    const int nloc = tid >> 4;
    const int n0   = blockIdx.x * 32 + nloc;
    const int n1   = n0 + 16;

    {
        const int kk = tid >> 4;
        const int q  = tid & 15;
        c4s[q][kk] = reinterpret_cast<const float4*>(comm)[kk * 16 + q];
    }
    __syncthreads();

    const float LOR_MIN = (float)(1.0 + 1e-7);
    const float CLIP_LO = (float)(-1.0 + 1e-7);
    const float CLIP_HI = (float)(1.0 - 1e-7);

    const float4* A0 = reinterpret_cast<const float4*>(emb) + (size_t)n0 * 16;
    const float4* B0 = A0 + (size_t)NN * 16;
    const float4* C0 = B0 + (size_t)NN * 16;
    const float4* A1 = reinterpret_cast<const float4*>(emb) + (size_t)n1 * 16;
    const float4* B1 = A1 + (size_t)NN * 16;
    const float4* C1 = B1 + (size_t)NN * 16;

    float dE0 = 0.f, xn0 = 0.f, dL0 = 0.f, dS0 = 0.f;
    float dE1 = 0.f, xn1 = 0.f, dL1 = 0.f, dS1 = 0.f;
    float cn = 0.f;

    #pragma unroll
    for (int q = 0; q < 16; ++q) {
        float4 c = c4s[q][k];
        cn = fmaf(c.x, c.x, cn); cn = fmaf(c.y, c.y, cn);
        cn = fmaf(c.z, c.z, cn); cn = fmaf(c.w, c.w, cn);

        float4 a = A0[q];
        dE0 = fmaf(a.x, c.x, dE0); dE0 = fmaf(a.y, c.y, dE0);
        dE0 = fmaf(a.z, c.z, dE0); dE0 = fmaf(a.w, c.w, dE0);
        xn0 = fmaf(a.x, a.x, xn0); xn0 = fmaf(a.y, a.y, xn0);
        xn0 = fmaf(a.z, a.z, xn0); xn0 = fmaf(a.w, a.w, xn0);
        float4 b = B0[q];
        dL0 = fmaf(b.x, c.x, dL0); dL0 = fmaf(b.y, c.y, dL0);
        dL0 = fmaf(b.z, c.z, dL0); dL0 = fmaf(b.w, c.w, dL0);
        float4 d = C0[q];
        dS0 = fmaf(d.x, c.x, dS0); dS0 = fmaf(d.y, c.y, dS0);
        dS0 = fmaf(d.z, c.z, dS0); dS0 = fmaf(d.w, c.w, dS0);

        float4 a1 = A1[q];
        dE1 = fmaf(a1.x, c.x, dE1); dE1 = fmaf(a1.y, c.y, dE1);
        dE1 = fmaf(a1.z, c.z, dE1); dE1 = fmaf(a1.w, c.w, dE1);
        xn1 = fmaf(a1.x, a1.x, xn1); xn1 = fmaf(a1.y, a1.y, xn1);
        xn1 = fmaf(a1.z, a1.z, xn1); xn1 = fmaf(a1.w, a1.w, xn1);
        float4 b1 = B1[q];
        dL1 = fmaf(b1.x, c.x, dL1); dL1 = fmaf(b1.y, c.y, dL1);
        dL1 = fmaf(b1.z, c.z, dL1); dL1 = fmaf(b1.w, c.w, dL1);
        float4 d1 = C1[q];
        dS1 = fmaf(d1.x, c.x, dS1); dS1 = fmaf(d1.y, c.y, dS1);
        dS1 = fmaf(d1.z, c.z, dS1); dS1 = fmaf(d1.w, c.w, dS1);
    }

    const float c00 = c4s[0][k].x;

    float d2_0 = fmaxf(xn0 - 2.f * dE0 + cn, 0.f);
    float d2_1 = fmaxf(xn1 - 2.f * dE1 + cn, 0.f);

    float lip0 = dL0 - 2.f * B0[0].x * c00;
    float lip1 = dL1 - 2.f * B1[0].x * c00;
    float dl0 = acoshf(fmaxf(-lip0, LOR_MIN));
    float dl1 = acoshf(fmaxf(-lip1, LOR_MIN));
    d2_0 = fmaf(dl0, dl0, d2_0);
    d2_1 = fmaf(dl1, dl1, d2_1);

    float ds0 = acosf(fminf(fmaxf(dS0, CLIP_LO), CLIP_HI));
    float ds1 = acosf(fminf(fmaxf(dS1, CLIP_LO), CLIP_HI));
    d2_0 = fmaf(ds0, ds0, d2_0);
    d2_1 = fmaf(ds1, ds1, d2_1);

    const float dn0 = sqrtf(d2_0);
    const float dn1 = sqrtf(d2_1);

    float m0 = dn0, m1 = dn1;
    #pragma unroll
    for (int off = 8; off >= 1; off >>= 1) {
        m0 = fmaxf(m0, __shfl_xor_sync(0xffffffffu, m0, off, 16));
        m1 = fmaxf(m1, __shfl_xor_sync(0xffffffffu, m1, off, 16));
    }
    float e0 = expf(dn0 - m0);
    float e1 = expf(dn1 - m1);
    float es0 = e0, es1 = e1;
    #pragma unroll
    for (int off = 8; off >= 1; off >>= 1) {
        es0 += __shfl_xor_sync(0xffffffffu, es0, off, 16);
        es1 += __shfl_xor_sync(0xffffffffu, es1, off, 16);
    }
    const float pi0 = e0 / es0;
    const float pi1 = e1 / es1;

    const float a  = alpha_p[0];
    const float c1 = a * (1.f / ((float)KC * (float)NN));
    const float c2 = 1.f / ((float)KC * (float)KC * (float)NN);  // sum_k pi == 1

    const int ns = k >> 3;
    const int g  = k & 7;

    {
        __nv_bfloat16 h = __float2bfloat16(pi0);
        __nv_bfloat16 l = __float2bfloat16(pi0 - __bfloat162float(h));
        int jm = n0 & 15, ksg = n0 >> 4;
        int rg = jm >> 3, t = (jm & 7) >> 1, hf = jm & 1;
        size_t u = ((size_t)(ksg * 2 + ns) * 32 + (g * 4 + t)) * 4 + rg * 2 + hf;
        g_Bhi[u] = __bfloat16_as_ushort(h);
        g_Blo[u] = __bfloat16_as_ushort(l);
        g_v[(size_t)n0 * KC + k] = fmaf(c1, pi0, -c2);
    }
    {
        __nv_bfloat16 h = __float2bfloat16(pi1);
        __nv_bfloat16 l = __float2bfloat16(pi1 - __bfloat162float(h));
        int jm = n1 & 15, ksg = n1 >> 4;
        int rg = jm >> 3, t = (jm & 7) >> 1, hf = jm & 1;
        size_t u = ((size_t)(ksg * 2 + ns) * 32 + (g * 4 + t)) * 4 + rg * 2 + hf;
        g_Bhi[u] = __bfloat16_as_ushort(h);
        g_Blo[u] = __bfloat16_as_ushort(l);
        g_v[(size_t)n1 * KC + k] = fmaf(c1, pi1, -c2);
    }
}

// ------------------------------------------------------------------
// Kernel 2: bf16 mma.sync, 3-term split, ALL-REGISTER mainloop.
// Warp owns mi=warp (16 rows), ki=0..3. A frags loaded directly from R
// (LDG->cvt->mma, no smem, no barriers). B frags loaded coalesced from
// the pre-formatted L2-resident arrays. item = m*128 + jc (jc inner):
// accumulators live across the block's range; epilogue at m boundaries.
// ------------------------------------------------------------------
__global__ void __launch_bounds__(TPB, 2)
bilinear_kernel(const float* __restrict__ R) {
    __shared__ float red[TPB];

    const int tid  = threadIdx.x;
    const int warp = tid >> 5;
    const int lane = tid & 31;
    const int g    = lane >> 2;
    const int t    = lane & 3;
    const int b    = blockIdx.x;

    const int start = (int)(((long long)b * NITEMS) / GRIDB);
    const int end   = (int)(((long long)(b + 1) * NITEMS) / GRIDB);

    float acc0[4] = {0.f, 0.f, 0.f, 0.f};   // ns=0
    float acc1[4] = {0.f, 0.f, 0.f, 0.f};   // ns=1
    float scalar = 0.f;

    for (int item = start; item < end; ++item) {
        const int m  = item >> 7;       // 0..63 (outer)
        const int jc = item & 127;      // 0..127 (inner)

        // ---- B fragments: coalesced LDG.64 from L2-resident arrays ----
        uint2 Bh[4][2], Bl[4][2];
        #pragma unroll
        for (int ki = 0; ki < 4; ++ki) {
            #pragma unroll
            for (int ns = 0; ns < 2; ++ns) {
                size_t bi = (((size_t)(jc * 4 + ki) * 2 + ns) * 32 + lane) * 4;
                Bh[ki][ns] = *reinterpret_cast<const uint2*>(g_Bhi + bi);
                Bl[ki][ns] = *reinterpret_cast<const uint2*>(g_Blo + bi);
            }
        }

        // ---- A: 16 independent LDG.64 (this warp's own subtiles) ----
        const float* base = R + (size_t)(m * MT + warp * 16 + g) * NN
                              + jc * KT + 2 * t;
        float2 x0[4], x1[4], x2[4], x3[4];
        #pragma unroll
        for (int ki = 0; ki < 4; ++ki) {
            const float* p = base + ki * 16;
            x0[ki] = *reinterpret_cast<const float2*>(p);
            x1[ki] = *reinterpret_cast<const float2*>(p + 8 * NN);
            x2[ki] = *reinterpret_cast<const float2*>(p + 8);
            x3[ki] = *reinterpret_cast<const float2*>(p + 8 * NN + 8);
        }

        // ---- cvt + mma, all in registers ----
        #pragma unroll
        for (int ki = 0; ki < 4; ++ki) {
            uint32_t h0 = bf2(x0[ki].x, x0[ki].y);
            uint32_t h1 = bf2(x1[ki].x, x1[ki].y);
            uint32_t h2 = bf2(x2[ki].x, x2[ki].y);
            uint32_t h3 = bf2(x3[ki].x, x3[ki].y);
            uint32_t l0 = bf2lo(x0[ki].x, x0[ki].y, h0);
            uint32_t l1 = bf2lo(x1[ki].x, x1[ki].y, h1);
            uint32_t l2 = bf2lo(x2[ki].x, x2[ki].y, h2);
            uint32_t l3 = bf2lo(x3[ki].x, x3[ki].y, h3);
            mma_bf16(acc0, h0, h1, h2, h3, Bh[ki][0].x, Bh[ki][0].y);
            mma_bf16(acc0, l0, l1, l2, l3, Bh[ki][0].x, Bh[ki][0].y);
            mma_bf16(acc0, h0, h1, h2, h3, Bl[ki][0].x, Bl[ki][0].y);
            mma_bf16(acc1, h0, h1, h2, h3, Bh[ki][1].x, Bh[ki][1].y);
            mma_bf16(acc1, l0, l1, l2, l3, Bh[ki][1].x, Bh[ki][1].y);
            mma_bf16(acc1, h0, h1, h2, h3, Bl[ki][1].x, Bl[ki][1].y);
        }

        // ---- epilogue at m-range end: contract T with v ----
        if (item + 1 == end || ((item + 1) >> 7) != m) {
            const int row = m * MT + warp * 16 + g;
            const float2* v0 = reinterpret_cast<const float2*>(g_v + (size_t)row * KC);
            const float2* v8 = reinterpret_cast<const float2*>(g_v + (size_t)(row + 8) * KC);
            float2 va = v0[t], vb = v8[t];            // ns0 cols 2t,2t+1
            float2 vc = v0[4 + t], vd = v8[4 + t];    // ns1 cols 8+2t
            scalar = fmaf(acc0[0], va.x, scalar);
            scalar = fmaf(acc0[1], va.y, scalar);
            scalar = fmaf(acc0[2], vb.x, scalar);
            scalar = fmaf(acc0[3], vb.y, scalar);
            scalar = fmaf(acc1[0], vc.x, scalar);
            scalar = fmaf(acc1[1], vc.y, scalar);
            scalar = fmaf(acc1[2], vd.x, scalar);
            scalar = fmaf(acc1[3], vd.y, scalar);
            acc0[0] = acc0[1] = acc0[2] = acc0[3] = 0.f;
            acc1[0] = acc1[1] = acc1[2] = acc1[3] = 0.f;
        }
    }

    // block reduction (fixed tree -> deterministic)
    red[tid] = scalar;
    __syncthreads();
    #pragma unroll
    for (int off = TPB / 2; off >= 1; off >>= 1) {
        if (tid < off) red[tid] += red[tid + off];
        __syncthreads();
    }
    if (tid == 0) g_partials[b] = red[0];
}

// ------------------------------------------------------------------
// Kernel 3: finalize
// ------------------------------------------------------------------
__global__ void __launch_bounds__(256)
finalize_kernel(float* __restrict__ out) {
    __shared__ float red[256];
    const int tid = threadIdx.x;
    float a = 0.f;
    for (int i = tid; i < GRIDB; i += 256) a += g_partials[i];
    red[tid] = a;
    __syncthreads();
    #pragma unroll
    for (int off = 128; off >= 1; off >>= 1) {
        if (tid < off) red[tid] += red[tid + off];
        __syncthreads();
    }
    if (tid == 0) out[0] = red[0];
}

// ------------------------------------------------------------------
extern "C" void kernel_launch(void* const* d_in, const int* in_sizes, int n_in,
                              void* d_out, int out_size) {
    const float* emb   = (const float*)d_in[0];   // (3, 8192, 64)
    const float* comm  = (const float*)d_in[1];   // (16, 64)
    const float* ricci = (const float*)d_in[2];   // (8192, 8192)
    const float* alpha = (const float*)d_in[3];   // scalar
    float* out = (float*)d_out;

    pi_kernel<<<NN / 32, 256>>>(emb, comm, alpha);
    bilinear_kernel<<<GRIDB, TPB>>>(ricci);
    finalize_kernel<<<1, 256>>>(out);
}

// round 17
// speedup vs baseline: 2.1480x; 1.0350x over previous
#include <cuda_runtime.h>
#include <cuda_bf16.h>
#include <cstdint>
#include <cstddef>

#define NN 8192
#define KC 16
#define DD 64

#define MT 128                       // rows per item (8 warps x 16)
#define KT 64                        // j-cols per item (4 ki subtiles)
#define NM (NN / MT)                 // 64
#define NJC (NN / KT)                // 128
#define NITEMS (NM * NJC)            // 8192 (item = m*128 + jc; jc inner)
#define GRIDB 296                    // 2 blocks/SM * 148
#define TPB 256

// U (pi) in bf16 mma-B fragment layout: per (ksg, ns, lane) one uint2 {b0,b1}
// ushort index = ((ksg*2+ns)*32 + lane)*4 + reg*2 + half   (ksg = j/16)
static __device__ __align__(16) unsigned short g_Bhi[(NN / 16) * 2 * 32 * 4];
static __device__ __align__(16) unsigned short g_Blo[(NN / 16) * 2 * 32 * 4];
static __device__ __align__(16) float g_v[NN * KC];    // v[i][k]
static __device__ float g_partials[GRIDB];

// ------------------------------------------------------------------
// helpers
// ------------------------------------------------------------------
__device__ __forceinline__ uint32_t bf2(float lo, float hi) {
    uint32_t r;
    asm("cvt.rn.bf16x2.f32 %0, %1, %2;" : "=r"(r) : "f"(hi), "f"(lo));
    return r;   // low 16 bits = lo, high = hi
}
__device__ __forceinline__ uint32_t bf2lo(float x0, float x1, uint32_t h) {
    float h0 = __uint_as_float(h << 16);
    float h1 = __uint_as_float(h & 0xffff0000u);
    return bf2(x0 - h0, x1 - h1);
}
__device__ __forceinline__ void mma_bf16(float* c, uint32_t a0, uint32_t a1,
                                         uint32_t a2, uint32_t a3,
                                         uint32_t b0, uint32_t b1) {
    asm volatile(
        "mma.sync.aligned.m16n8k16.row.col.f32.bf16.bf16.f32 "
        "{%0,%1,%2,%3}, {%4,%5,%6,%7}, {%8,%9}, {%0,%1,%2,%3};"
        : "+f"(c[0]), "+f"(c[1]), "+f"(c[2]), "+f"(c[3])
        : "r"(a0), "r"(a1), "r"(a2), "r"(a3), "r"(b0), "r"(b1));
}

// ------------------------------------------------------------------
// Kernel 1: distances -> softmax pi -> U bf16 hi/lo frag layout + v
// 256 threads = 16 nodes x 16 k-lanes, ONE node per thread; grid 512
// (2x the warps of the R16 version -> latency-bound chains hidden)
// ------------------------------------------------------------------
__global__ void __launch_bounds__(256)
pi_kernel(const float* __restrict__ emb,    // (3, NN, DD)
          const float* __restrict__ comm,   // (KC, DD)
          const float* __restrict__ alpha_p) {
    __shared__ float4 c4s[DD / 4][KC];
    const int tid  = threadIdx.x;
    const int k    = tid & 15;
    const int nloc = tid >> 4;              // 0..15
    const int n    = blockIdx.x * 16 + nloc;

    {
        const int kk = tid >> 4;
        const int q  = tid & 15;
        c4s[q][kk] = reinterpret_cast<const float4*>(comm)[kk * 16 + q];
    }
    __syncthreads();

    const float LOR_MIN = (float)(1.0 + 1e-7);
    const float CLIP_LO = (float)(-1.0 + 1e-7);
    const float CLIP_HI = (float)(1.0 - 1e-7);

    const float4* A0 = reinterpret_cast<const float4*>(emb) + (size_t)n * 16;
    const float4* B0 = A0 + (size_t)NN * 16;
    const float4* C0 = B0 + (size_t)NN * 16;

    float dE = 0.f, xn = 0.f, dL = 0.f, dS = 0.f, cn = 0.f;

    #pragma unroll
    for (int q = 0; q < 16; ++q) {
        float4 c = c4s[q][k];
        cn = fmaf(c.x, c.x, cn); cn = fmaf(c.y, c.y, cn);
        cn = fmaf(c.z, c.z, cn); cn = fmaf(c.w, c.w, cn);

        float4 a = A0[q];
        dE = fmaf(a.x, c.x, dE); dE = fmaf(a.y, c.y, dE);
        dE = fmaf(a.z, c.z, dE); dE = fmaf(a.w, c.w, dE);
        xn = fmaf(a.x, a.x, xn); xn = fmaf(a.y, a.y, xn);
        xn = fmaf(a.z, a.z, xn); xn = fmaf(a.w, a.w, xn);
        float4 b = B0[q];
        dL = fmaf(b.x, c.x, dL); dL = fmaf(b.y, c.y, dL);
        dL = fmaf(b.z, c.z, dL); dL = fmaf(b.w, c.w, dL);
        float4 d = C0[q];
        dS = fmaf(d.x, c.x, dS); dS = fmaf(d.y, c.y, dS);
        dS = fmaf(d.z, c.z, dS); dS = fmaf(d.w, c.w, dS);
    }

    float d2 = fmaxf(xn - 2.f * dE + cn, 0.f);
    float lip = dL - 2.f * B0[0].x * c4s[0][k].x;
    float dl  = acoshf(fmaxf(-lip, LOR_MIN));
    d2 = fmaf(dl, dl, d2);
    float ds = acosf(fminf(fmaxf(dS, CLIP_LO), CLIP_HI));
    d2 = fmaf(ds, ds, d2);
    const float dn = sqrtf(d2);

    float m = dn;
    #pragma unroll
    for (int off = 8; off >= 1; off >>= 1)
        m = fmaxf(m, __shfl_xor_sync(0xffffffffu, m, off, 16));
    float e = expf(dn - m);
    float es = e;
    #pragma unroll
    for (int off = 8; off >= 1; off >>= 1)
        es += __shfl_xor_sync(0xffffffffu, es, off, 16);
    const float pi = e / es;

    const float a  = alpha_p[0];
    const float c1 = a * (1.f / ((float)KC * (float)NN));
    const float c2 = 1.f / ((float)KC * (float)KC * (float)NN);  // sum_k pi == 1

    const int ns = k >> 3;
    const int g  = k & 7;

    __nv_bfloat16 h = __float2bfloat16(pi);
    __nv_bfloat16 l = __float2bfloat16(pi - __bfloat162float(h));
    int jm = n & 15, ksg = n >> 4;
    int rg = jm >> 3, t = (jm & 7) >> 1, hf = jm & 1;
    size_t u = ((size_t)(ksg * 2 + ns) * 32 + (g * 4 + t)) * 4 + rg * 2 + hf;
    g_Bhi[u] = __bfloat16_as_ushort(h);
    g_Blo[u] = __bfloat16_as_ushort(l);
    g_v[(size_t)n * KC + k] = fmaf(c1, pi, -c2);
}

// ------------------------------------------------------------------
// Kernel 2: bf16 mma.sync, 3-term split, ALL-REGISTER mainloop.
// Warp owns mi=warp (16 rows), ki=0..3. A frags loaded directly from R
// (LDG->cvt->mma, no smem, no barriers). B frags loaded coalesced from
// the pre-formatted L2-resident arrays. item = m*128 + jc (jc inner):
// accumulators live across the block's range; epilogue at m boundaries.
// Split accumulator chains (hi*hi vs lo-corrections) halve the serial
// mma RAW depth per item.
// ------------------------------------------------------------------
__global__ void __launch_bounds__(TPB, 2)
bilinear_kernel(const float* __restrict__ R) {
    __shared__ float red[TPB];

    const int tid  = threadIdx.x;
    const int warp = tid >> 5;
    const int lane = tid & 31;
    const int g    = lane >> 2;
    const int t    = lane & 3;
    const int b    = blockIdx.x;

    const int start = (int)(((long long)b * NITEMS) / GRIDB);
    const int end   = (int)(((long long)(b + 1) * NITEMS) / GRIDB);

    float acc0h[4] = {0.f, 0.f, 0.f, 0.f};   // ns=0, hi*hi chain
    float acc0l[4] = {0.f, 0.f, 0.f, 0.f};   // ns=0, lo-correction chain
    float acc1h[4] = {0.f, 0.f, 0.f, 0.f};   // ns=1, hi*hi chain
    float acc1l[4] = {0.f, 0.f, 0.f, 0.f};   // ns=1, lo-correction chain
    float scalar = 0.f;

    for (int item = start; item < end; ++item) {
        const int m  = item >> 7;       // 0..63 (outer)
        const int jc = item & 127;      // 0..127 (inner)

        // ---- B fragments: coalesced LDG.64 from L2-resident arrays ----
        uint2 Bh[4][2], Bl[4][2];
        #pragma unroll
        for (int ki = 0; ki < 4; ++ki) {
            #pragma unroll
            for (int ns = 0; ns < 2; ++ns) {
                size_t bi = (((size_t)(jc * 4 + ki) * 2 + ns) * 32 + lane) * 4;
                Bh[ki][ns] = *reinterpret_cast<const uint2*>(g_Bhi + bi);
                Bl[ki][ns] = *reinterpret_cast<const uint2*>(g_Blo + bi);
            }
        }

        // ---- A: 16 independent LDG.64 (this warp's own subtiles) ----
        const float* base = R + (size_t)(m * MT + warp * 16 + g) * NN
                              + jc * KT + 2 * t;
        float2 x0[4], x1[4], x2[4], x3[4];
        #pragma unroll
        for (int ki = 0; ki < 4; ++ki) {
            const float* p = base + ki * 16;
            x0[ki] = *reinterpret_cast<const float2*>(p);
            x1[ki] = *reinterpret_cast<const float2*>(p + 8 * NN);
            x2[ki] = *reinterpret_cast<const float2*>(p + 8);
            x3[ki] = *reinterpret_cast<const float2*>(p + 8 * NN + 8);
        }

        // ---- cvt + mma, all in registers; two chains per ns ----
        #pragma unroll
        for (int ki = 0; ki < 4; ++ki) {
            uint32_t h0 = bf2(x0[ki].x, x0[ki].y);
            uint32_t h1 = bf2(x1[ki].x, x1[ki].y);
            uint32_t h2 = bf2(x2[ki].x, x2[ki].y);
            uint32_t h3 = bf2(x3[ki].x, x3[ki].y);
            uint32_t l0 = bf2lo(x0[ki].x, x0[ki].y, h0);
            uint32_t l1 = bf2lo(x1[ki].x, x1[ki].y, h1);
            uint32_t l2 = bf2lo(x2[ki].x, x2[ki].y, h2);
            uint32_t l3 = bf2lo(x3[ki].x, x3[ki].y, h3);
            mma_bf16(acc0h, h0, h1, h2, h3, Bh[ki][0].x, Bh[ki][0].y);
            mma_bf16(acc0l, l0, l1, l2, l3, Bh[ki][0].x, Bh[ki][0].y);
            mma_bf16(acc0l, h0, h1, h2, h3, Bl[ki][0].x, Bl[ki][0].y);
            mma_bf16(acc1h, h0, h1, h2, h3, Bh[ki][1].x, Bh[ki][1].y);
            mma_bf16(acc1l, l0, l1, l2, l3, Bh[ki][1].x, Bh[ki][1].y);
            mma_bf16(acc1l, h0, h1, h2, h3, Bl[ki][1].x, Bl[ki][1].y);
        }

        // ---- epilogue at m-range end: contract T with v ----
        if (item + 1 == end || ((item + 1) >> 7) != m) {
            const int row = m * MT + warp * 16 + g;
            const float2* v0 = reinterpret_cast<const float2*>(g_v + (size_t)row * KC);
            const float2* v8 = reinterpret_cast<const float2*>(g_v + (size_t)(row + 8) * KC);
            float2 va = v0[t], vb = v8[t];            // ns0 cols 2t,2t+1
            float2 vc = v0[4 + t], vd = v8[4 + t];    // ns1 cols 8+2t
            scalar = fmaf(acc0h[0] + acc0l[0], va.x, scalar);
            scalar = fmaf(acc0h[1] + acc0l[1], va.y, scalar);
            scalar = fmaf(acc0h[2] + acc0l[2], vb.x, scalar);
            scalar = fmaf(acc0h[3] + acc0l[3], vb.y, scalar);
            scalar = fmaf(acc1h[0] + acc1l[0], vc.x, scalar);
            scalar = fmaf(acc1h[1] + acc1l[1], vc.y, scalar);
            scalar = fmaf(acc1h[2] + acc1l[2], vd.x, scalar);
            scalar = fmaf(acc1h[3] + acc1l[3], vd.y, scalar);
            #pragma unroll
            for (int q = 0; q < 4; ++q) {
                acc0h[q] = 0.f; acc0l[q] = 0.f;
                acc1h[q] = 0.f; acc1l[q] = 0.f;
            }
        }
    }

    // block reduction (fixed tree -> deterministic)
    red[tid] = scalar;
    __syncthreads();
    #pragma unroll
    for (int off = TPB / 2; off >= 1; off >>= 1) {
        if (tid < off) red[tid] += red[tid + off];
        __syncthreads();
    }
    if (tid == 0) g_partials[b] = red[0];
}

// ------------------------------------------------------------------
// Kernel 3: finalize
// ------------------------------------------------------------------
__global__ void __launch_bounds__(256)
finalize_kernel(float* __restrict__ out) {
    __shared__ float red[256];
    const int tid = threadIdx.x;
    float a = 0.f;
    for (int i = tid; i < GRIDB; i += 256) a += g_partials[i];
    red[tid] = a;
    __syncthreads();
    #pragma unroll
    for (int off = 128; off >= 1; off >>= 1) {
        if (tid < off) red[tid] += red[tid + off];
        __syncthreads();
    }
    if (tid == 0) out[0] = red[0];
}

// ------------------------------------------------------------------
extern "C" void kernel_launch(void* const* d_in, const int* in_sizes, int n_in,
                              void* d_out, int out_size) {
    const float* emb   = (const float*)d_in[0];   // (3, 8192, 64)
    const float* comm  = (const float*)d_in[1];   // (16, 64)
    const float* ricci = (const float*)d_in[2];   // (8192, 8192)
    const float* alpha = (const float*)d_in[3];   // scalar
    float* out = (float*)d_out;

    pi_kernel<<<NN / 16, 256>>>(emb, comm, alpha);
    bilinear_kernel<<<GRIDB, TPB>>>(ricci);
    finalize_kernel<<<1, 256>>>(out);
}